// round 4
// baseline (speedup 1.0000x reference)
#include <cuda_runtime.h>
#include <math.h>

#define BB 32
#define SS 256
#define TT 256
#define HH 4096
#define EE 64
#define EPS_V 1e-6f

// ---------------- scratch (no allocations allowed) ----------------
__device__ float g_m[BB * HH];        // sum over s of input_embeds  (512 KB)
__device__ float g_cond[BB * EE];     // cond[:, :E]                 (8 KB)
__device__ float g_pbpd[TT * HH];     // prompt_base + prompt_delta  (4 MB)
__device__ unsigned int g_Hbits;      // max|H_slice| as uint bits
__device__ unsigned int g_Dbits;      // max|d_slice| as uint bits

// ---------------- K0: reset atomic-max scalars ----------------
__global__ void k_reset() {
    g_Hbits = 0u;
    g_Dbits = 0u;
}

// ---------------- K1: m[b,h] = sum_s x[b,s,h] ----------------
// grid (HH/256, BB), block 256. Coalesced across h, loop over s.
__global__ __launch_bounds__(256) void k_reduce_s(const float* __restrict__ x) {
    int b = blockIdx.y;
    int h = blockIdx.x * 256 + threadIdx.x;
    const float* p = x + (size_t)b * SS * HH + h;
    float acc = 0.f;
#pragma unroll 8
    for (int s = 0; s < SS; ++s) acc += p[(size_t)s * HH];
    g_m[b * HH + h] = acc;
}

// ---------------- K2: pbpd = pb + pd (float4) ----------------
// grid TT*HH/1024, block 256
__global__ __launch_bounds__(256) void k_pbpd(const float* __restrict__ pb,
                                              const float* __restrict__ pd) {
    int i = blockIdx.x * 256 + threadIdx.x;
    float4 a = ((const float4*)pb)[i];
    float4 c = ((const float4*)pd)[i];
    float4 r = make_float4(a.x + c.x, a.y + c.y, a.z + c.z, a.w + c.w);
    ((float4*)g_pbpd)[i] = r;
}

// ---------------- K3: cond[b,e] = (1/S) * sum_h m[b,h]*W[e,h], e < E ----------------
// grid (EE, BB), block 256
__global__ __launch_bounds__(256) void k_cond(const float* __restrict__ W) {
    int e = blockIdx.x, b = blockIdx.y;
    const float4* w = (const float4*)(W + (size_t)e * HH);
    const float4* mm = (const float4*)(g_m + (size_t)b * HH);
    float acc = 0.f;
#pragma unroll
    for (int i = threadIdx.x; i < HH / 4; i += 256) {
        float4 a = w[i], c = mm[i];
        acc += a.x * c.x + a.y * c.y + a.z * c.z + a.w * c.w;
    }
#pragma unroll
    for (int o = 16; o > 0; o >>= 1) acc += __shfl_down_sync(0xffffffffu, acc, o);
    __shared__ float sred[8];
    if ((threadIdx.x & 31) == 0) sred[threadIdx.x >> 5] = acc;
    __syncthreads();
    if (threadIdx.x < 8) {
        float v = sred[threadIdx.x];
#pragma unroll
        for (int o = 4; o > 0; o >>= 1) v += __shfl_down_sync(0xffu, v, o);
        if (threadIdx.x == 0) g_cond[b * EE + e] = v * (1.0f / SS);
    }
}

// ---------------- K4: global scales via atomicMax on float bits ----------------
// Non-negative floats order identically as uint bit patterns.
// grid 256, block 256, grid-stride.
__global__ __launch_bounds__(256) void k_scales(const float* __restrict__ pb,
                                                const float* __restrict__ pd) {
    float hmax = 0.f, dmax = 0.f;
    int stride = gridDim.x * blockDim.x;
    int base = blockIdx.x * blockDim.x + threadIdx.x;
    for (int i = base; i < BB * TT * EE; i += stride) {
        int e = i & (EE - 1);
        int t = (i >> 6) & (TT - 1);
        int b = i >> 14;
        hmax = fmaxf(hmax, fabsf(pb[t * HH + e] + g_cond[b * EE + e]));
    }
    for (int i = base; i < TT * EE; i += stride) {
        int e = i & (EE - 1);
        int t = i >> 6;
        dmax = fmaxf(dmax, fabsf(pd[t * HH + e]));
    }
#pragma unroll
    for (int o = 16; o > 0; o >>= 1) {
        hmax = fmaxf(hmax, __shfl_down_sync(0xffffffffu, hmax, o));
        dmax = fmaxf(dmax, __shfl_down_sync(0xffffffffu, dmax, o));
    }
    __shared__ float shm[8], sdm[8];
    if ((threadIdx.x & 31) == 0) {
        shm[threadIdx.x >> 5] = hmax;
        sdm[threadIdx.x >> 5] = dmax;
    }
    __syncthreads();
    if (threadIdx.x == 0) {
        float hv = shm[0], dv = sdm[0];
#pragma unroll
        for (int j = 1; j < 8; ++j) {
            hv = fmaxf(hv, shm[j]);
            dv = fmaxf(dv, sdm[j]);
        }
        atomicMax(&g_Hbits, __float_as_uint(hv));
        atomicMax(&g_Dbits, __float_as_uint(dv));
    }
}

// ---------------- K5: routing + output ----------------
// grid (TT, BB), block 256. One block = one (b,t) output row of 4096 floats.
__global__ __launch_bounds__(256) void k_out(const float* __restrict__ pb,
                                             const float* __restrict__ pd,
                                             const float* __restrict__ limes,
                                             const float* __restrict__ shv,
                                             const float* __restrict__ gamma,
                                             float* __restrict__ out) {
    int t = blockIdx.x, b = blockIdx.y;
    int tid = threadIdx.x;

    __shared__ float s_log[EE];
    __shared__ float s_w[4];
    __shared__ int s_idx[4];

    float invHs = 1.f / fmaxf(__uint_as_float(g_Hbits), EPS_V);
    float invDs = 1.f / fmaxf(__uint_as_float(g_Dbits), EPS_V);

    if (tid < EE) {
        float l = 0.5f * (pb[t * HH + tid] + g_cond[b * EE + tid]) * invHs +
                  0.5f * pd[t * HH + tid] * invDs;
        s_log[tid] = l;
    }
    __syncthreads();

    if (tid == 0) {
        // serial top-4, strict > keeps earliest index on ties (matches lax.top_k)
        float bv0 = -3.4e38f, bv1 = -3.4e38f, bv2 = -3.4e38f, bv3 = -3.4e38f;
        int bi0 = 0, bi1 = 0, bi2 = 0, bi3 = 0;
#pragma unroll
        for (int e = 0; e < EE; ++e) {
            float v = s_log[e];
            if (v > bv0) {
                bv3 = bv2; bi3 = bi2; bv2 = bv1; bi2 = bi1;
                bv1 = bv0; bi1 = bi0; bv0 = v; bi0 = e;
            } else if (v > bv1) {
                bv3 = bv2; bi3 = bi2; bv2 = bv1; bi2 = bi1; bv1 = v; bi1 = e;
            } else if (v > bv2) {
                bv3 = bv2; bi3 = bi2; bv2 = v; bi2 = e;
            } else if (v > bv3) {
                bv3 = v; bi3 = e;
            }
        }
        // softmax over the selected 4 == softmax(all)/sum(top4) (Z cancels)
        float e0 = 1.0f;
        float e1 = __expf(bv1 - bv0);
        float e2 = __expf(bv2 - bv0);
        float e3 = __expf(bv3 - bv0);
        float inv = 1.0f / (e0 + e1 + e2 + e3);
        s_w[0] = e0 * inv; s_w[1] = e1 * inv; s_w[2] = e2 * inv; s_w[3] = e3 * inv;
        s_idx[0] = bi0; s_idx[1] = bi1; s_idx[2] = bi2; s_idx[3] = bi3;
    }
    __syncthreads();

    float g = 1.f / (1.f + __expf(-gamma[0]));
    float omg = 1.f - g;
    float w0 = s_w[0] * omg, w1 = s_w[1] * omg, w2 = s_w[2] * omg, w3 = s_w[3] * omg;
    const float4* L0 = (const float4*)(limes + (size_t)s_idx[0] * HH);
    const float4* L1 = (const float4*)(limes + (size_t)s_idx[1] * HH);
    const float4* L2 = (const float4*)(limes + (size_t)s_idx[2] * HH);
    const float4* L3 = (const float4*)(limes + (size_t)s_idx[3] * HH);
    const float4* P = (const float4*)(g_pbpd + (size_t)t * HH);
    const float4* SH = (const float4*)shv;
    float4* O = (float4*)(out + ((size_t)b * TT + t) * HH);

#pragma unroll
    for (int i = tid; i < HH / 4; i += 256) {
        float4 p = P[i];
        float4 a = L0[i], c = L1[i], d = L2[i], e = L3[i], s = SH[i];
        float4 r;
        r.x = p.x * (w0 * a.x + w1 * c.x + w2 * d.x + w3 * e.x + g * s.x);
        r.y = p.y * (w0 * a.y + w1 * c.y + w2 * d.y + w3 * e.y + g * s.y);
        r.z = p.z * (w0 * a.z + w1 * c.z + w2 * d.z + w3 * e.z + g * s.z);
        r.w = p.w * (w0 * a.w + w1 * c.w + w2 * d.w + w3 * e.w + g * s.w);
        O[i] = r;
    }
}

extern "C" void kernel_launch(void* const* d_in, const int* in_sizes, int n_in,
                              void* d_out, int out_size) {
    const float* x     = (const float*)d_in[0];  // input_embeds (B,S,H)
    const float* pb    = (const float*)d_in[1];  // prompt_base  (T,H)
    const float* pd    = (const float*)d_in[2];  // prompt_delta (T,H)
    const float* limes = (const float*)d_in[3];  // LiMEs        (E,H)
    const float* shv   = (const float*)d_in[4];  // LiME_shared  (H,)
    const float* gamma = (const float*)d_in[5];  // gamma        (1,)
    const float* W     = (const float*)d_in[6];  // W_proj       (H,H)
    float* out = (float*)d_out;                  // (B,T,H) f32

    k_reset<<<1, 1>>>();
    k_reduce_s<<<dim3(HH / 256, BB), 256>>>(x);
    k_pbpd<<<TT * HH / 1024, 256>>>(pb, pd);
    k_cond<<<dim3(EE, BB), 256>>>(W);
    k_scales<<<256, 256>>>(pb, pd);
    k_out<<<dim3(TT, BB), 256>>>(pb, pd, limes, shv, gamma, out);
}